// round 5
// baseline (speedup 1.0000x reference)
#include <cuda_runtime.h>

#define NB 4
#define NT 1024
#define NC 768
#define NH 12
#define ND 64

typedef unsigned long long u64;

// packed fp32x2 helpers (Blackwell FFMA2 — only reachable via PTX)
__device__ __forceinline__ u64 pk2(float x) {
    u64 r;
    asm("mov.b64 %0, {%1, %1};" : "=l"(r) : "f"(x));
    return r;
}
__device__ __forceinline__ void fma2(u64& d, u64 a, u64 b) {
    asm("fma.rn.f32x2 %0, %1, %2, %0;" : "+l"(d) : "l"(a), "l"(b));
}
__device__ __forceinline__ void unpk2(float& lo, float& hi, u64 v) {
    asm("mov.b64 {%0, %1}, %2;" : "=f"(lo), "=f"(hi) : "l"(v));
}

// ---------------- scratch (device globals; no allocation allowed) ----------
__device__ float g_q[NB*NH*NT*ND];
__device__ float g_k[NB*NH*NT*ND];
__device__ float g_v[NB*NH*NT*ND];
__device__ float g_yh[NB*NT*NC];   // y pre-proj, [B,T,H*D] layout

// ---------------- QKV GEMM: [4096,768] @ [768,2304], fused bias + scatter --
__global__ __launch_bounds__(256, 1)
void k_qkv(const float* __restrict__ x, const float* __restrict__ W,
           const float* __restrict__ bq)
{
    __shared__ float As[8][128];
    __shared__ float Bs[8][132];
    const int tid = threadIdx.x;
    const int m0 = blockIdx.y * 128;
    const int n0 = blockIdx.x * 128;
    const int ty = tid >> 4, tx = tid & 15;

    u64 acc2[8][4];
#pragma unroll
    for (int i = 0; i < 8; i++)
#pragma unroll
        for (int j = 0; j < 4; j++) acc2[i][j] = 0ull;

    const int arow = tid >> 1, ac4 = (tid & 1) * 4;
    const int brow = tid >> 5, bc4 = (tid & 31) * 4;

    for (int k0 = 0; k0 < 768; k0 += 8) {
        float4 a4 = *(const float4*)(x + (size_t)(m0 + arow) * 768 + k0 + ac4);
        float4 b4 = *(const float4*)(W + (size_t)(k0 + brow) * 2304 + n0 + bc4);
        As[ac4 + 0][arow] = a4.x; As[ac4 + 1][arow] = a4.y;
        As[ac4 + 2][arow] = a4.z; As[ac4 + 3][arow] = a4.w;
        *(float4*)&Bs[brow][bc4] = b4;
        __syncthreads();
#pragma unroll
        for (int kk = 0; kk < 8; kk++) {
            float af[8];
            *(float4*)&af[0] = *(const float4*)&As[kk][ty * 8];
            *(float4*)&af[4] = *(const float4*)&As[kk][ty * 8 + 4];
            ulonglong2 b01 = *(const ulonglong2*)&Bs[kk][tx * 8];
            ulonglong2 b23 = *(const ulonglong2*)&Bs[kk][tx * 8 + 4];
            u64 bp[4] = {b01.x, b01.y, b23.x, b23.y};
#pragma unroll
            for (int i = 0; i < 8; i++) {
                const u64 ap = pk2(af[i]);
#pragma unroll
                for (int j = 0; j < 4; j++)
                    fma2(acc2[i][j], ap, bp[j]);
            }
        }
        __syncthreads();
    }

#pragma unroll
    for (int i = 0; i < 8; i++) {
        const int m = m0 + ty * 8 + i;
        const int b = m >> 10, t = m & 1023;
#pragma unroll
        for (int j = 0; j < 4; j++) {
            float lo, hi;
            unpk2(lo, hi, acc2[i][j]);
#pragma unroll
            for (int u = 0; u < 2; u++) {
                const int n = n0 + tx * 8 + j * 2 + u;
                const float v = (u ? hi : lo) + bq[n];
                const int part = n / 768;
                const int rem  = n - part * 768;
                const int h = rem >> 6, d = rem & 63;
                float* dst = (part == 0) ? g_q : (part == 1) ? g_k : g_v;
                dst[(size_t)(((b * NH + h) * NT + t)) * ND + d] = v;
            }
        }
    }
}

// ---------------- proj GEMM: g_yh [4096,768] @ W_proj [768,768] -> y -------
__global__ __launch_bounds__(256, 1)
void k_proj(const float* __restrict__ W, const float* __restrict__ bp,
            float* __restrict__ out)
{
    __shared__ float As[8][128];
    __shared__ float Bs[8][132];
    const int tid = threadIdx.x;
    const int m0 = blockIdx.y * 128;
    const int n0 = blockIdx.x * 128;
    const int ty = tid >> 4, tx = tid & 15;

    u64 acc2[8][4];
#pragma unroll
    for (int i = 0; i < 8; i++)
#pragma unroll
        for (int j = 0; j < 4; j++) acc2[i][j] = 0ull;

    const int arow = tid >> 1, ac4 = (tid & 1) * 4;
    const int brow = tid >> 5, bc4 = (tid & 31) * 4;

    for (int k0 = 0; k0 < 768; k0 += 8) {
        float4 a4 = *(const float4*)(g_yh + (size_t)(m0 + arow) * 768 + k0 + ac4);
        float4 b4 = *(const float4*)(W + (size_t)(k0 + brow) * 768 + n0 + bc4);
        As[ac4 + 0][arow] = a4.x; As[ac4 + 1][arow] = a4.y;
        As[ac4 + 2][arow] = a4.z; As[ac4 + 3][arow] = a4.w;
        *(float4*)&Bs[brow][bc4] = b4;
        __syncthreads();
#pragma unroll
        for (int kk = 0; kk < 8; kk++) {
            float af[8];
            *(float4*)&af[0] = *(const float4*)&As[kk][ty * 8];
            *(float4*)&af[4] = *(const float4*)&As[kk][ty * 8 + 4];
            ulonglong2 b01 = *(const ulonglong2*)&Bs[kk][tx * 8];
            ulonglong2 b23 = *(const ulonglong2*)&Bs[kk][tx * 8 + 4];
            u64 bpr[4] = {b01.x, b01.y, b23.x, b23.y};
#pragma unroll
            for (int i = 0; i < 8; i++) {
                const u64 ap = pk2(af[i]);
#pragma unroll
                for (int j = 0; j < 4; j++)
                    fma2(acc2[i][j], ap, bpr[j]);
            }
        }
        __syncthreads();
    }

#pragma unroll
    for (int i = 0; i < 8; i++) {
        const int m = m0 + ty * 8 + i;
#pragma unroll
        for (int j = 0; j < 4; j++) {
            float lo, hi;
            unpk2(lo, hi, acc2[i][j]);
            const int n = n0 + tx * 8 + j * 2;
            out[(size_t)m * 768 + n]     = lo + bp[n];
            out[(size_t)m * 768 + n + 1] = hi + bp[n + 1];
        }
    }
}

// ---------------- fused attention: per (b,h, 64 t-rows) --------------------
#define SPAD 68
#define SMEMB (4 * 64 * SPAD * 4)

__global__ __launch_bounds__(256, 1)
void k_attn(const float* __restrict__ bias, const float* __restrict__ mask,
            float* __restrict__ attn)
{
    extern __shared__ float sm[];
    float* Qs = sm;                  // [d][t]
    float* Ks = sm + 64 * SPAD;      // [d][s]
    float* Vs = sm + 2 * 64 * SPAD;  // [s][d]
    float* Ps = sm + 3 * 64 * SPAD;  // [t][s]

    const int tid = threadIdx.x;
    const int ty = tid >> 4, tx = tid & 15;
    const int b = blockIdx.z, h = blockIdx.y;
    const int t0 = blockIdx.x * 64;
    const int bh = b * NH + h;
    const float scale = 0.125f;

    // load Q tile [64 t][64 d] -> Qs[d][t]
    const float* qg = g_q + (size_t)(bh * NT + t0) * ND;
    for (int e = tid; e < 1024; e += 256) {
        const int t = e >> 4, d4 = (e & 15) * 4;
        float4 v = *(const float4*)(qg + t * 64 + d4);
        Qs[(d4 + 0) * SPAD + t] = v.x;
        Qs[(d4 + 1) * SPAD + t] = v.y;
        Qs[(d4 + 2) * SPAD + t] = v.z;
        Qs[(d4 + 3) * SPAD + t] = v.w;
    }

    u64 yacc2[4][2];
#pragma unroll
    for (int i = 0; i < 4; i++) { yacc2[i][0] = 0ull; yacc2[i][1] = 0ull; }
    float rs[4] = {0.f, 0.f, 0.f, 0.f};

    for (int st = 0; st < 16; st++) {
        const int s0 = st * 64;
        const float* kg = g_k + (size_t)(bh * NT + s0) * ND;
        const float* vg = g_v + (size_t)(bh * NT + s0) * ND;
        for (int e = tid; e < 1024; e += 256) {
            const int s = e >> 4, d4 = (e & 15) * 4;
            float4 kv = *(const float4*)(kg + s * 64 + d4);
            Ks[(d4 + 0) * SPAD + s] = kv.x;
            Ks[(d4 + 1) * SPAD + s] = kv.y;
            Ks[(d4 + 2) * SPAD + s] = kv.z;
            Ks[(d4 + 3) * SPAD + s] = kv.w;
            float4 vv = *(const float4*)(vg + s * 64 + d4);
            *(float4*)&Vs[s * SPAD + d4] = vv;
        }
        __syncthreads();

        // S = Q K^T (4x4 microtile, packed f32x2 along s)
        u64 sa2[4][2];
#pragma unroll
        for (int i = 0; i < 4; i++) { sa2[i][0] = 0ull; sa2[i][1] = 0ull; }
#pragma unroll 16
        for (int d = 0; d < 64; d++) {
            float4 aq = *(const float4*)&Qs[d * SPAD + ty * 4];
            ulonglong2 kb = *(const ulonglong2*)&Ks[d * SPAD + tx * 4];
            const float a[4] = {aq.x, aq.y, aq.z, aq.w};
#pragma unroll
            for (int i = 0; i < 4; i++) {
                const u64 ap = pk2(a[i]);
                fma2(sa2[i][0], ap, kb.x);
                fma2(sa2[i][1], ap, kb.y);
            }
        }

        // p = exp(scale*S + bias + mask); write unnormalized attn; stash in Ps
#pragma unroll
        for (int i = 0; i < 4; i++) {
            float s01l, s01h, s23l, s23h;
            unpk2(s01l, s01h, sa2[i][0]);
            unpk2(s23l, s23h, sa2[i][1]);
            const int t = t0 + ty * 4 + i;
            const float4 bb = *(const float4*)(bias + ((size_t)bh * NT + t) * NT + s0 + tx * 4);
            const float4 mm = *(const float4*)(mask + ((size_t)b  * NT + t) * NT + s0 + tx * 4);
            float4 p;
            p.x = expf(fmaf(s01l, scale, bb.x + mm.x));
            p.y = expf(fmaf(s01h, scale, bb.y + mm.y));
            p.z = expf(fmaf(s23l, scale, bb.z + mm.z));
            p.w = expf(fmaf(s23h, scale, bb.w + mm.w));
            rs[i] += (p.x + p.y) + (p.z + p.w);
            *(float4*)(attn + ((size_t)bh * NT + t) * NT + s0 + tx * 4) = p;
            *(float4*)&Ps[(ty * 4 + i) * SPAD + tx * 4] = p;
        }
        __syncthreads();

        // y += P V (packed f32x2 along d)
#pragma unroll 16
        for (int ss = 0; ss < 64; ss++) {
            ulonglong2 vv2 = *(const ulonglong2*)&Vs[ss * SPAD + tx * 4];
#pragma unroll
            for (int i = 0; i < 4; i++) {
                const u64 pp = pk2(Ps[(ty * 4 + i) * SPAD + ss]);
                fma2(yacc2[i][0], pp, vv2.x);
                fma2(yacc2[i][1], pp, vv2.y);
            }
        }
        __syncthreads();
    }

    // rowsum reduction across the 16 lanes sharing each t-row
#pragma unroll
    for (int i = 0; i < 4; i++) {
        float v = rs[i];
        v += __shfl_down_sync(0xffffffffu, v, 8, 16);
        v += __shfl_down_sync(0xffffffffu, v, 4, 16);
        v += __shfl_down_sync(0xffffffffu, v, 2, 16);
        v += __shfl_down_sync(0xffffffffu, v, 1, 16);
        v  = __shfl_sync(0xffffffffu, v, 0, 16);
        rs[i] = 1.0f / v;
    }

    // write normalized y head output to g_yh [B,T,H*D]
#pragma unroll
    for (int i = 0; i < 4; i++) {
        const int t = t0 + ty * 4 + i;
        float y0, y1, y2, y3;
        unpk2(y0, y1, yacc2[i][0]);
        unpk2(y2, y3, yacc2[i][1]);
        float4 o;
        o.x = y0 * rs[i];
        o.y = y1 * rs[i];
        o.z = y2 * rs[i];
        o.w = y3 * rs[i];
        *(float4*)(g_yh + ((size_t)b * NT + t) * NC + h * ND + tx * 4) = o;
    }

    // normalize attn in place (each thread touches only its own prior stores)
    for (int st = 0; st < 16; st++) {
#pragma unroll
        for (int i = 0; i < 4; i++) {
            const int t = t0 + ty * 4 + i;
            float4* p4 = (float4*)(attn + ((size_t)bh * NT + t) * NT + st * 64 + tx * 4);
            float4 v = *p4;
            v.x *= rs[i]; v.y *= rs[i]; v.z *= rs[i]; v.w *= rs[i];
            *p4 = v;
        }
    }
}

// ---------------- launch ---------------------------------------------------
extern "C" void kernel_launch(void* const* d_in, const int* in_sizes, int n_in,
                              void* d_out, int out_size)
{
    const float* x     = (const float*)d_in[0];
    const float* mask  = (const float*)d_in[1];
    const float* bias  = (const float*)d_in[2];
    const float* Wqkv  = (const float*)d_in[3];
    const float* bqkv  = (const float*)d_in[4];
    const float* Wproj = (const float*)d_in[5];
    const float* bproj = (const float*)d_in[6];

    float* y    = (float*)d_out;
    float* attn = y + (size_t)NB * NT * NC;

    cudaFuncSetAttribute(k_attn, cudaFuncAttributeMaxDynamicSharedMemorySize, SMEMB);

    k_qkv <<<dim3(2304 / 128, 4096 / 128), 256>>>(x, Wqkv, bqkv);
    k_attn<<<dim3(NT / 64, NH, NB), 256, SMEMB>>>(bias, mask, attn);
    k_proj<<<dim3(768 / 128, 4096 / 128), 256>>>(Wproj, bproj, y);
}

// round 8
// speedup vs baseline: 1.8095x; 1.8095x over previous
#include <cuda_runtime.h>
#include <cuda_bf16.h>
#include <cstdint>

#define NB 4
#define NT 1024
#define NC 768
#define NH 12
#define ND 64

// ---------------- scratch (device globals; no allocation allowed) ----------
__device__ float g_q[NB*NH*NT*ND];
__device__ float g_k[NB*NH*NT*ND];
__device__ float g_v[NB*NH*NT*ND];
__device__ float g_yh[NB*NT*NC];   // y pre-proj, [B,T,H*D] layout

// bf16 split operands
__device__ __nv_bfloat16 g_xh[4096*768],  g_xl[4096*768];
__device__ __nv_bfloat16 g_wqh[2304*768], g_wql[2304*768];   // W_qkv^T  [N][K]
__device__ __nv_bfloat16 g_wph[768*768],  g_wpl[768*768];    // W_proj^T [N][K]
__device__ __nv_bfloat16 g_yhh[4096*768], g_yhl[4096*768];

// ===================== HMMA helpers (sm_80+ portable) ======================
__device__ __forceinline__ uint32_t smem_u32(const void* p) {
    uint32_t a;
    asm("{ .reg .u64 t; cvta.to.shared.u64 t, %1; cvt.u32.u64 %0, t; }" : "=r"(a) : "l"(p));
    return a;
}
__device__ __forceinline__ void ldsm4(uint32_t* r, uint32_t addr) {
    asm volatile("ldmatrix.sync.aligned.m8n8.x4.shared.b16 {%0,%1,%2,%3}, [%4];"
        : "=r"(r[0]), "=r"(r[1]), "=r"(r[2]), "=r"(r[3]) : "r"(addr));
}
__device__ __forceinline__ void ldsm2(uint32_t* r, uint32_t addr) {
    asm volatile("ldmatrix.sync.aligned.m8n8.x2.shared.b16 {%0,%1}, [%2];"
        : "=r"(r[0]), "=r"(r[1]) : "r"(addr));
}
__device__ __forceinline__ void mma16816(float* c, const uint32_t* a, const uint32_t* b) {
    asm volatile("mma.sync.aligned.m16n8k16.row.col.f32.bf16.bf16.f32 "
        "{%0,%1,%2,%3}, {%4,%5,%6,%7}, {%8,%9}, {%0,%1,%2,%3};"
        : "+f"(c[0]), "+f"(c[1]), "+f"(c[2]), "+f"(c[3])
        : "r"(a[0]), "r"(a[1]), "r"(a[2]), "r"(a[3]), "r"(b[0]), "r"(b[1]));
}
__device__ __forceinline__ void cpasync16(uint32_t dst, const void* src) {
    asm volatile("cp.async.cg.shared.global [%0], [%1], 16;" :: "r"(dst), "l"(src));
}
#define CP_COMMIT() asm volatile("cp.async.commit_group;" ::: "memory")

// ---------------- split fp32 -> bf16 hi/lo (elementwise) -------------------
__global__ __launch_bounds__(256)
void k_split(const float* __restrict__ in, __nv_bfloat16* __restrict__ oh,
             __nv_bfloat16* __restrict__ ol)
{
    const int i = (blockIdx.x * 256 + threadIdx.x) * 4;
    float4 v = *(const float4*)(in + i);
    __nv_bfloat16 h0 = __float2bfloat16(v.x), h1 = __float2bfloat16(v.y);
    __nv_bfloat16 h2 = __float2bfloat16(v.z), h3 = __float2bfloat16(v.w);
    __nv_bfloat162 hh0; hh0.x = h0; hh0.y = h1;
    __nv_bfloat162 hh1; hh1.x = h2; hh1.y = h3;
    *(__nv_bfloat162*)(oh + i)     = hh0;
    *(__nv_bfloat162*)(oh + i + 2) = hh1;
    __nv_bfloat162 ll0, ll1;
    ll0.x = __float2bfloat16(v.x - __bfloat162float(h0));
    ll0.y = __float2bfloat16(v.y - __bfloat162float(h1));
    ll1.x = __float2bfloat16(v.z - __bfloat162float(h2));
    ll1.y = __float2bfloat16(v.w - __bfloat162float(h3));
    *(__nv_bfloat162*)(ol + i)     = ll0;
    *(__nv_bfloat162*)(ol + i + 2) = ll1;
}

// ---------------- transpose + split: W[K=768][N] -> out[N][768] ------------
__global__ __launch_bounds__(256)
void k_splitT(const float* __restrict__ W, __nv_bfloat16* __restrict__ oh,
              __nv_bfloat16* __restrict__ ol, int Ncols)
{
    __shared__ float t[32][33];
    const int k0 = blockIdx.y * 32, n0 = blockIdx.x * 32;
    const int tx = threadIdx.x & 31, ty = threadIdx.x >> 5;  // 32x8
#pragma unroll
    for (int j = 0; j < 32; j += 8)
        t[ty + j][tx] = W[(size_t)(k0 + ty + j) * Ncols + n0 + tx];
    __syncthreads();
#pragma unroll
    for (int j = 0; j < 32; j += 8) {
        const float v = t[tx][ty + j];                       // = W[k0+tx][n0+ty+j]
        const __nv_bfloat16 h = __float2bfloat16(v);
        const size_t o = (size_t)(n0 + ty + j) * 768 + k0 + tx;
        oh[o] = h;
        ol[o] = __float2bfloat16(v - __bfloat162float(h));
    }
}

// ---------------- HMMA bf16x3 GEMM: 128x128 tiles, K=768 -------------------
// A[M][768] K-major (hi/lo), B[N][768] K-major (hi/lo).
// C[m][n] = sum_k A[m][k]*B[n][k] (+bias[n]); QKV=1 scatters to g_q/g_k/g_v.
#define PITCH   40                     // bf16 per smem row (80 B, conflict-free ldmatrix)
#define TILEB   (128 * PITCH * 2)      // 10240 B per operand tile
#define BUFB    (4 * TILEB)            // Ah, Al, Bh, Bl
#define GSMEM2  (2 * BUFB)             // 81920 B double-buffered
#define NCHUNK  24                     // 768 / 32

template<int QKV>
__global__ __launch_bounds__(256, 1)
void k_gemm(const __nv_bfloat16* __restrict__ Ah, const __nv_bfloat16* __restrict__ Al,
            const __nv_bfloat16* __restrict__ Bh, const __nv_bfloat16* __restrict__ Bl,
            const float* __restrict__ bias, float* __restrict__ outp)
{
    extern __shared__ char smem[];
    const uint32_t sb = smem_u32(smem);
    const int tid = threadIdx.x;
    const int wid = tid >> 5, lane = tid & 31;
    const int m0 = blockIdx.y * 128, n0 = blockIdx.x * 128;
    const int warp_m = (wid & 1) * 64, warp_n = (wid >> 1) * 32;

    const __nv_bfloat16* srcs[4] = {Ah, Al, Bh, Bl};

    // cp.async tile loader: 4 tiles x 512 x 16B, 8 per thread
    auto issue_load = [&](int c) {
        const int k0 = c * 32;
        const uint32_t dbase = sb + (c & 1) * BUFB;
#pragma unroll
        for (int i = 0; i < 8; i++) {
            const int idx = tid + i * 256;
            const int tl = idx >> 9, w = idx & 511;
            const int r = w >> 2, c8 = w & 3;
            const int rb = (tl < 2) ? m0 : n0;
            cpasync16(dbase + tl * TILEB + r * 80 + c8 * 16,
                      srcs[tl] + (size_t)(rb + r) * 768 + k0 + c8 * 8);
        }
        CP_COMMIT();
    };

    float acc[4][4][4];
#pragma unroll
    for (int mf = 0; mf < 4; mf++)
#pragma unroll
        for (int nf = 0; nf < 4; nf++)
#pragma unroll
            for (int e = 0; e < 4; e++) acc[mf][nf][e] = 0.f;

    // per-lane ldmatrix byte offsets
    const int rowA = (lane & 7) | (((lane >> 3) & 1) << 3);
    const uint32_t laneA = (uint32_t)(warp_m + rowA) * 80 + ((lane >> 4) << 4);
    const int l2 = lane & 15;
    const uint32_t laneB = (uint32_t)(warp_n + (l2 & 7)) * 80 + ((l2 >> 3) << 4);

    issue_load(0);

    for (int c = 0; c < NCHUNK; c++) {
        if (c + 1 < NCHUNK) {
            issue_load(c + 1);
            asm volatile("cp.async.wait_group 1;" ::: "memory");
        } else {
            asm volatile("cp.async.wait_group 0;" ::: "memory");
        }
        __syncthreads();

        const uint32_t base = sb + (c & 1) * BUFB;
        const uint32_t sAh = base,          sAl = base + TILEB;
        const uint32_t sBh = base + 2*TILEB, sBl = base + 3*TILEB;

#pragma unroll
        for (int ks = 0; ks < 32; ks += 16) {
            uint32_t ah[4][4], al[4][4], bh[4][2], bl[4][2];
#pragma unroll
            for (int mf = 0; mf < 4; mf++) {
                ldsm4(ah[mf], sAh + mf * 1280 + ks * 2 + laneA);
                ldsm4(al[mf], sAl + mf * 1280 + ks * 2 + laneA);
            }
#pragma unroll
            for (int nf = 0; nf < 4; nf++) {
                ldsm2(bh[nf], sBh + nf * 640 + ks * 2 + laneB);
                ldsm2(bl[nf], sBl + nf * 640 + ks * 2 + laneB);
            }
#pragma unroll
            for (int mf = 0; mf < 4; mf++)
#pragma unroll
                for (int nf = 0; nf < 4; nf++) {
                    mma16816(acc[mf][nf], ah[mf], bh[nf]);
                    mma16816(acc[mf][nf], ah[mf], bl[nf]);
                    mma16816(acc[mf][nf], al[mf], bh[nf]);
                }
        }
        __syncthreads();
    }

    // epilogue: lane holds C[m][n], m = warp_m+mf*16+lane/4(+8), n = warp_n+nf*8+(lane%4)*2
    const int lr = lane >> 2, lc = (lane & 3) * 2;
#pragma unroll
    for (int mf = 0; mf < 4; mf++) {
#pragma unroll
        for (int half = 0; half < 2; half++) {
            const int m = m0 + warp_m + mf * 16 + lr + half * 8;
#pragma unroll
            for (int nf = 0; nf < 4; nf++) {
                const int n = n0 + warp_n + nf * 8 + lc;
                const float v0 = acc[mf][nf][half * 2 + 0] + bias[n];
                const float v1 = acc[mf][nf][half * 2 + 1] + bias[n + 1];
                if (QKV) {
                    const int b = m >> 10, t = m & 1023;
                    const int part = n / 768;
                    const int rem  = n - part * 768;
                    const int h = rem >> 6, d = rem & 63;
                    float* dst = (part == 0) ? g_q : (part == 1) ? g_k : g_v;
                    float2 o; o.x = v0; o.y = v1;
                    *(float2*)(dst + ((size_t)((b * NH + h) * NT + t)) * ND + d) = o;
                } else {
                    float2 o; o.x = v0; o.y = v1;
                    *(float2*)(outp + (size_t)m * 768 + n) = o;
                }
            }
        }
    }
}

// ---------------- fused attention: per (b,h, 64 t-rows) [R2 scalar] --------
#define SPAD 68
#define SMEMB (4 * 64 * SPAD * 4)

__global__ __launch_bounds__(256, 1)
void k_attn(const float* __restrict__ bias, const float* __restrict__ mask,
            float* __restrict__ attn)
{
    extern __shared__ float sm[];
    float* Qs = sm;                  // [d][t]
    float* Ks = sm + 64 * SPAD;      // [d][s]
    float* Vs = sm + 2 * 64 * SPAD;  // [s][d]
    float* Ps = sm + 3 * 64 * SPAD;  // [t][s]

    const int tid = threadIdx.x;
    const int ty = tid >> 4, tx = tid & 15;
    const int b = blockIdx.z, h = blockIdx.y;
    const int t0 = blockIdx.x * 64;
    const int bh = b * NH + h;
    const float scale = 0.125f;

    const float* qg = g_q + (size_t)(bh * NT + t0) * ND;
    for (int e = tid; e < 1024; e += 256) {
        const int t = e >> 4, d4 = (e & 15) * 4;
        float4 v = *(const float4*)(qg + t * 64 + d4);
        Qs[(d4 + 0) * SPAD + t] = v.x;
        Qs[(d4 + 1) * SPAD + t] = v.y;
        Qs[(d4 + 2) * SPAD + t] = v.z;
        Qs[(d4 + 3) * SPAD + t] = v.w;
    }

    float yacc[4][4];
#pragma unroll
    for (int i = 0; i < 4; i++)
#pragma unroll
        for (int j = 0; j < 4; j++) yacc[i][j] = 0.f;
    float rs[4] = {0.f, 0.f, 0.f, 0.f};

    for (int st = 0; st < 16; st++) {
        const int s0 = st * 64;
        const float* kg = g_k + (size_t)(bh * NT + s0) * ND;
        const float* vg = g_v + (size_t)(bh * NT + s0) * ND;
        for (int e = tid; e < 1024; e += 256) {
            const int s = e >> 4, d4 = (e & 15) * 4;
            float4 kv = *(const float4*)(kg + s * 64 + d4);
            Ks[(d4 + 0) * SPAD + s] = kv.x;
            Ks[(d4 + 1) * SPAD + s] = kv.y;
            Ks[(d4 + 2) * SPAD + s] = kv.z;
            Ks[(d4 + 3) * SPAD + s] = kv.w;
            float4 vv = *(const float4*)(vg + s * 64 + d4);
            *(float4*)&Vs[s * SPAD + d4] = vv;
        }
        __syncthreads();

        float sa[4][4];
#pragma unroll
        for (int i = 0; i < 4; i++)
#pragma unroll
            for (int j = 0; j < 4; j++) sa[i][j] = 0.f;
#pragma unroll 16
        for (int d = 0; d < 64; d++) {
            float4 aq = *(const float4*)&Qs[d * SPAD + ty * 4];
            float4 bk = *(const float4*)&Ks[d * SPAD + tx * 4];
            const float a[4] = {aq.x, aq.y, aq.z, aq.w};
            const float c[4] = {bk.x, bk.y, bk.z, bk.w};
#pragma unroll
            for (int i = 0; i < 4; i++)
#pragma unroll
                for (int j = 0; j < 4; j++)
                    sa[i][j] = fmaf(a[i], c[j], sa[i][j]);
        }

#pragma unroll
        for (int i = 0; i < 4; i++) {
            const int t = t0 + ty * 4 + i;
            const float4 bb = *(const float4*)(bias + ((size_t)bh * NT + t) * NT + s0 + tx * 4);
            const float4 mm = *(const float4*)(mask + ((size_t)b  * NT + t) * NT + s0 + tx * 4);
            float4 p;
            p.x = expf(fmaf(sa[i][0], scale, bb.x + mm.x));
            p.y = expf(fmaf(sa[i][1], scale, bb.y + mm.y));
            p.z = expf(fmaf(sa[i][2], scale, bb.z + mm.z));
            p.w = expf(fmaf(sa[i][3], scale, bb.w + mm.w));
            rs[i] += (p.x + p.y) + (p.z + p.w);
            *(float4*)(attn + ((size_t)bh * NT + t) * NT + s0 + tx * 4) = p;
            *(float4*)&Ps[(ty * 4 + i) * SPAD + tx * 4] = p;
        }
        __syncthreads();

#pragma unroll 16
        for (int ss = 0; ss < 64; ss++) {
            float4 vv = *(const float4*)&Vs[ss * SPAD + tx * 4];
#pragma unroll
            for (int i = 0; i < 4; i++) {
                const float p = Ps[(ty * 4 + i) * SPAD + ss];
                yacc[i][0] = fmaf(p, vv.x, yacc[i][0]);
                yacc[i][1] = fmaf(p, vv.y, yacc[i][1]);
                yacc[i][2] = fmaf(p, vv.z, yacc[i][2]);
                yacc[i][3] = fmaf(p, vv.w, yacc[i][3]);
            }
        }
        __syncthreads();
    }

#pragma unroll
    for (int i = 0; i < 4; i++) {
        float v = rs[i];
        v += __shfl_down_sync(0xffffffffu, v, 8, 16);
        v += __shfl_down_sync(0xffffffffu, v, 4, 16);
        v += __shfl_down_sync(0xffffffffu, v, 2, 16);
        v += __shfl_down_sync(0xffffffffu, v, 1, 16);
        v  = __shfl_sync(0xffffffffu, v, 0, 16);
        rs[i] = 1.0f / v;
    }

#pragma unroll
    for (int i = 0; i < 4; i++) {
        const int t = t0 + ty * 4 + i;
        float4 o;
        o.x = yacc[i][0] * rs[i];
        o.y = yacc[i][1] * rs[i];
        o.z = yacc[i][2] * rs[i];
        o.w = yacc[i][3] * rs[i];
        *(float4*)(g_yh + ((size_t)b * NT + t) * NC + h * ND + tx * 4) = o;
    }

    for (int st = 0; st < 16; st++) {
#pragma unroll
        for (int i = 0; i < 4; i++) {
            const int t = t0 + ty * 4 + i;
            float4* p4 = (float4*)(attn + ((size_t)bh * NT + t) * NT + st * 64 + tx * 4);
            float4 v = *p4;
            v.x *= rs[i]; v.y *= rs[i]; v.z *= rs[i]; v.w *= rs[i];
            *p4 = v;
        }
    }
}

// ---------------- launch ---------------------------------------------------
extern "C" void kernel_launch(void* const* d_in, const int* in_sizes, int n_in,
                              void* d_out, int out_size)
{
    const float* x     = (const float*)d_in[0];
    const float* mask  = (const float*)d_in[1];
    const float* bias  = (const float*)d_in[2];
    const float* Wqkv  = (const float*)d_in[3];
    const float* bqkv  = (const float*)d_in[4];
    const float* Wproj = (const float*)d_in[5];
    const float* bproj = (const float*)d_in[6];

    float* y    = (float*)d_out;
    float* attn = y + (size_t)NB * NT * NC;

    cudaFuncSetAttribute(k_attn,    cudaFuncAttributeMaxDynamicSharedMemorySize, SMEMB);
    cudaFuncSetAttribute(k_gemm<1>, cudaFuncAttributeMaxDynamicSharedMemorySize, GSMEM2);
    cudaFuncSetAttribute(k_gemm<0>, cudaFuncAttributeMaxDynamicSharedMemorySize, GSMEM2);

    __nv_bfloat16 *xh, *xl, *wqh, *wql, *wph, *wpl, *yhh, *yhl;
    float *yh;
    cudaGetSymbolAddress((void**)&xh,  g_xh);  cudaGetSymbolAddress((void**)&xl,  g_xl);
    cudaGetSymbolAddress((void**)&wqh, g_wqh); cudaGetSymbolAddress((void**)&wql, g_wql);
    cudaGetSymbolAddress((void**)&wph, g_wph); cudaGetSymbolAddress((void**)&wpl, g_wpl);
    cudaGetSymbolAddress((void**)&yhh, g_yhh); cudaGetSymbolAddress((void**)&yhl, g_yhl);
    cudaGetSymbolAddress((void**)&yh,  g_yh);

    k_split <<<4096 * 768 / 1024, 256>>>(x, xh, xl);
    k_splitT<<<dim3(2304 / 32, 768 / 32), 256>>>(Wqkv, wqh, wql, 2304);
    k_splitT<<<dim3(768 / 32,  768 / 32), 256>>>(Wproj, wph, wpl, 768);

    k_gemm<1><<<dim3(2304 / 128, 4096 / 128), 256, GSMEM2>>>(xh, xl, wqh, wql, bqkv, nullptr);
    k_attn  <<<dim3(NT / 64, NH, NB), 256, SMEMB>>>(bias, mask, attn);
    k_split <<<4096 * 768 / 1024, 256>>>(yh, yhh, yhl);
    k_gemm<0><<<dim3(768 / 128, 4096 / 128), 256, GSMEM2>>>(yhh, yhl, wph, wpl, bproj, y);
}

// round 10
// speedup vs baseline: 2.3402x; 1.2933x over previous
#include <cuda_runtime.h>
#include <cuda_bf16.h>
#include <cstdint>

#define NB 4
#define NT 1024
#define NC 768
#define NH 12
#define ND 64

// ---------------- scratch (device globals; no allocation allowed) ----------
__device__ float g_yh[NB*NT*NC];   // y pre-proj, [B,T,H*D] layout

// bf16 split operands
__device__ __nv_bfloat16 g_xh[4096*768],  g_xl[4096*768];
__device__ __nv_bfloat16 g_wqh[2304*768], g_wql[2304*768];   // W_qkv^T  [N][K]
__device__ __nv_bfloat16 g_wph[768*768],  g_wpl[768*768];    // W_proj^T [N][K]
__device__ __nv_bfloat16 g_yhh[4096*768], g_yhl[4096*768];
// q,k: [b,h,t,d]; v transposed: [b,h,d,s]
__device__ __nv_bfloat16 g_qh[NB*NH*NT*ND], g_ql[NB*NH*NT*ND];
__device__ __nv_bfloat16 g_kh[NB*NH*NT*ND], g_kl[NB*NH*NT*ND];
__device__ __nv_bfloat16 g_vth[NB*NH*ND*NT], g_vtl[NB*NH*ND*NT];

// ===================== HMMA helpers (sm_80+ portable) ======================
__device__ __forceinline__ uint32_t smem_u32(const void* p) {
    uint32_t a;
    asm("{ .reg .u64 t; cvta.to.shared.u64 t, %1; cvt.u32.u64 %0, t; }" : "=r"(a) : "l"(p));
    return a;
}
__device__ __forceinline__ void ldsm4(uint32_t* r, uint32_t addr) {
    asm volatile("ldmatrix.sync.aligned.m8n8.x4.shared.b16 {%0,%1,%2,%3}, [%4];"
        : "=r"(r[0]), "=r"(r[1]), "=r"(r[2]), "=r"(r[3]) : "r"(addr));
}
__device__ __forceinline__ void ldsm2(uint32_t* r, uint32_t addr) {
    asm volatile("ldmatrix.sync.aligned.m8n8.x2.shared.b16 {%0,%1}, [%2];"
        : "=r"(r[0]), "=r"(r[1]) : "r"(addr));
}
__device__ __forceinline__ void mma16816(float* c, const uint32_t* a, const uint32_t* b) {
    asm volatile("mma.sync.aligned.m16n8k16.row.col.f32.bf16.bf16.f32 "
        "{%0,%1,%2,%3}, {%4,%5,%6,%7}, {%8,%9}, {%0,%1,%2,%3};"
        : "+f"(c[0]), "+f"(c[1]), "+f"(c[2]), "+f"(c[3])
        : "r"(a[0]), "r"(a[1]), "r"(a[2]), "r"(a[3]), "r"(b[0]), "r"(b[1]));
}
__device__ __forceinline__ void cpasync16(uint32_t dst, const void* src) {
    asm volatile("cp.async.cg.shared.global [%0], [%1], 16;" :: "r"(dst), "l"(src));
}
#define CP_COMMIT() asm volatile("cp.async.commit_group;" ::: "memory")

// fast exp: 2^t via magic round + deg-5 poly; t must be >= -126 (clamped by caller)
__device__ __forceinline__ float fexp2(float t) {
    const float magic = 12582912.0f;   // 1.5 * 2^23
    float r = t + magic;
    float f = t - (r - magic);         // f in [-0.5, 0.5]
    float p = 0.00133335581f;
    p = fmaf(p, f, 0.00961812911f);
    p = fmaf(p, f, 0.0555041087f);
    p = fmaf(p, f, 0.240226507f);
    p = fmaf(p, f, 0.693147182f);
    p = fmaf(p, f, 1.0f);
    return __int_as_float(__float_as_int(p) + (__float_as_int(r) << 23));
}

// ---------------- split fp32 -> bf16 hi/lo (elementwise) -------------------
__global__ __launch_bounds__(256)
void k_split(const float* __restrict__ in, __nv_bfloat16* __restrict__ oh,
             __nv_bfloat16* __restrict__ ol)
{
    const int i = (blockIdx.x * 256 + threadIdx.x) * 4;
    float4 v = *(const float4*)(in + i);
    __nv_bfloat16 h0 = __float2bfloat16(v.x), h1 = __float2bfloat16(v.y);
    __nv_bfloat16 h2 = __float2bfloat16(v.z), h3 = __float2bfloat16(v.w);
    __nv_bfloat162 hh0; hh0.x = h0; hh0.y = h1;
    __nv_bfloat162 hh1; hh1.x = h2; hh1.y = h3;
    *(__nv_bfloat162*)(oh + i)     = hh0;
    *(__nv_bfloat162*)(oh + i + 2) = hh1;
    __nv_bfloat162 ll0, ll1;
    ll0.x = __float2bfloat16(v.x - __bfloat162float(h0));
    ll0.y = __float2bfloat16(v.y - __bfloat162float(h1));
    ll1.x = __float2bfloat16(v.z - __bfloat162float(h2));
    ll1.y = __float2bfloat16(v.w - __bfloat162float(h3));
    *(__nv_bfloat162*)(ol + i)     = ll0;
    *(__nv_bfloat162*)(ol + i + 2) = ll1;
}

// ---------------- transpose + split: W[K=768][N] -> out[N][768] ------------
__global__ __launch_bounds__(256)
void k_splitT(const float* __restrict__ W, __nv_bfloat16* __restrict__ oh,
              __nv_bfloat16* __restrict__ ol, int Ncols)
{
    __shared__ float t[32][33];
    const int k0 = blockIdx.y * 32, n0 = blockIdx.x * 32;
    const int tx = threadIdx.x & 31, ty = threadIdx.x >> 5;  // 32x8
#pragma unroll
    for (int j = 0; j < 32; j += 8)
        t[ty + j][tx] = W[(size_t)(k0 + ty + j) * Ncols + n0 + tx];
    __syncthreads();
#pragma unroll
    for (int j = 0; j < 32; j += 8) {
        const float v = t[tx][ty + j];
        const __nv_bfloat16 h = __float2bfloat16(v);
        const size_t o = (size_t)(n0 + ty + j) * 768 + k0 + tx;
        oh[o] = h;
        ol[o] = __float2bfloat16(v - __bfloat162float(h));
    }
}

// ---------------- HMMA bf16x3 GEMM: 128x128 tiles, K=768 -------------------
#define PITCH   40
#define TILEB   (128 * PITCH * 2)
#define BUFB    (4 * TILEB)
#define GSMEM2  (2 * BUFB)
#define NCHUNK  24

template<int QKV>
__global__ __launch_bounds__(256, 1)
void k_gemm(const __nv_bfloat16* __restrict__ Ah, const __nv_bfloat16* __restrict__ Al,
            const __nv_bfloat16* __restrict__ Bh, const __nv_bfloat16* __restrict__ Bl,
            const float* __restrict__ bias, float* __restrict__ outp)
{
    extern __shared__ char smem[];
    const uint32_t sb = smem_u32(smem);
    const int tid = threadIdx.x;
    const int wid = tid >> 5, lane = tid & 31;
    const int m0 = blockIdx.y * 128, n0 = blockIdx.x * 128;
    const int warp_m = (wid & 1) * 64, warp_n = (wid >> 1) * 32;

    const __nv_bfloat16* srcs[4] = {Ah, Al, Bh, Bl};

    auto issue_load = [&](int c) {
        const int k0 = c * 32;
        const uint32_t dbase = sb + (c & 1) * BUFB;
#pragma unroll
        for (int i = 0; i < 8; i++) {
            const int idx = tid + i * 256;
            const int tl = idx >> 9, w = idx & 511;
            const int r = w >> 2, c8 = w & 3;
            const int rb = (tl < 2) ? m0 : n0;
            cpasync16(dbase + tl * TILEB + r * 80 + c8 * 16,
                      srcs[tl] + (size_t)(rb + r) * 768 + k0 + c8 * 8);
        }
        CP_COMMIT();
    };

    float acc[4][4][4];
#pragma unroll
    for (int mf = 0; mf < 4; mf++)
#pragma unroll
        for (int nf = 0; nf < 4; nf++)
#pragma unroll
            for (int e = 0; e < 4; e++) acc[mf][nf][e] = 0.f;

    const int rowA = (lane & 7) | (((lane >> 3) & 1) << 3);
    const uint32_t laneA = (uint32_t)(warp_m + rowA) * 80 + ((lane >> 4) << 4);
    const int l2 = lane & 15;
    const uint32_t laneB = (uint32_t)(warp_n + (l2 & 7)) * 80 + ((l2 >> 3) << 4);

    issue_load(0);

    for (int c = 0; c < NCHUNK; c++) {
        if (c + 1 < NCHUNK) {
            issue_load(c + 1);
            asm volatile("cp.async.wait_group 1;" ::: "memory");
        } else {
            asm volatile("cp.async.wait_group 0;" ::: "memory");
        }
        __syncthreads();

        const uint32_t base = sb + (c & 1) * BUFB;
        const uint32_t sAh = base,          sAl = base + TILEB;
        const uint32_t sBh = base + 2*TILEB, sBl = base + 3*TILEB;

#pragma unroll
        for (int ks = 0; ks < 32; ks += 16) {
            uint32_t ah[4][4], al[4][4], bh[4][2], bl[4][2];
#pragma unroll
            for (int mf = 0; mf < 4; mf++) {
                ldsm4(ah[mf], sAh + mf * 1280 + ks * 2 + laneA);
                ldsm4(al[mf], sAl + mf * 1280 + ks * 2 + laneA);
            }
#pragma unroll
            for (int nf = 0; nf < 4; nf++) {
                ldsm2(bh[nf], sBh + nf * 640 + ks * 2 + laneB);
                ldsm2(bl[nf], sBl + nf * 640 + ks * 2 + laneB);
            }
#pragma unroll
            for (int mf = 0; mf < 4; mf++)
#pragma unroll
                for (int nf = 0; nf < 4; nf++) {
                    mma16816(acc[mf][nf], ah[mf], bh[nf]);
                    mma16816(acc[mf][nf], ah[mf], bl[nf]);
                    mma16816(acc[mf][nf], al[mf], bh[nf]);
                }
        }
        __syncthreads();
    }

    const int lr = lane >> 2, lc = (lane & 3) * 2;
#pragma unroll
    for (int mf = 0; mf < 4; mf++) {
#pragma unroll
        for (int half = 0; half < 2; half++) {
            const int m = m0 + warp_m + mf * 16 + lr + half * 8;
#pragma unroll
            for (int nf = 0; nf < 4; nf++) {
                const int n = n0 + warp_n + nf * 8 + lc;
                const float v0 = acc[mf][nf][half * 2 + 0] + bias[n];
                const float v1 = acc[mf][nf][half * 2 + 1] + bias[n + 1];
                if (QKV) {
                    const int b = m >> 10, t = m & 1023;
                    const int part = n / 768;
                    const int rem  = n - part * 768;
                    const int h = rem >> 6, d = rem & 63;
                    const __nv_bfloat16 h0 = __float2bfloat16(v0);
                    const __nv_bfloat16 l0 = __float2bfloat16(v0 - __bfloat162float(h0));
                    const __nv_bfloat16 h1 = __float2bfloat16(v1);
                    const __nv_bfloat16 l1 = __float2bfloat16(v1 - __bfloat162float(h1));
                    if (part < 2) {
                        const size_t o = ((size_t)((b * NH + h) * NT + t)) * ND + d;
                        __nv_bfloat162 hh; hh.x = h0; hh.y = h1;
                        __nv_bfloat162 ll; ll.x = l0; ll.y = l1;
                        if (part == 0) { *(__nv_bfloat162*)(g_qh + o) = hh; *(__nv_bfloat162*)(g_ql + o) = ll; }
                        else           { *(__nv_bfloat162*)(g_kh + o) = hh; *(__nv_bfloat162*)(g_kl + o) = ll; }
                    } else {
                        const size_t o = ((size_t)((b * NH + h) * ND + d)) * NT + t;
                        g_vth[o] = h0; g_vtl[o] = l0;
                        g_vth[o + NT] = h1; g_vtl[o + NT] = l1;
                    }
                } else {
                    float2 o; o.x = v0; o.y = v1;
                    *(float2*)(outp + (size_t)m * 768 + n) = o;
                }
            }
        }
    }
}

// ---------------- HMMA attention: per (b,h, 128 t-rows) --------------------
// smem byte offsets (pitches: Q/K rows 144B, Vt/P rows 272B)
#define AQH 0
#define AQL 18432
#define AKH 36864
#define AKL 55296
#define AVH 73728
#define AVL 91136
#define APH 108544
#define APL 143360
#define ARS 178176            // 2*128 floats
#define AINV 179200           // 128 floats
#define SMEMA 179712

__global__ __launch_bounds__(256, 1)
void k_attn(const float* __restrict__ bias, const float* __restrict__ mask,
            float* __restrict__ attn)
{
    extern __shared__ char sa[];
    const uint32_t sb = smem_u32(sa);
    float* RS  = (float*)(sa + ARS);
    float* INV = (float*)(sa + AINV);

    const int tid = threadIdx.x;
    const int wid = tid >> 5, lane = tid & 31;
    const int warp_m = wid & 3, warp_n = wid >> 2;   // 4 x 2
    const int b = blockIdx.z, h = blockIdx.y;
    const int t0 = blockIdx.x * 128;
    const int bh = b * NH + h;

    const float SC2E = 0.18033688f;    // 0.125 * log2(e)
    const float L2E  = 1.44269504f;

    // Q tile load (hi+lo): 128 rows x 128B, 2048 16B chunks
#pragma unroll
    for (int i = 0; i < 4; i++) {
        const int idx = tid + i * 256;
        const int r = idx >> 3, c = idx & 7;
        const size_t src = (size_t)(bh * NT + t0 + r) * ND + c * 8;
        cpasync16(sb + AQH + r * 144 + c * 16, g_qh + src);
        cpasync16(sb + AQL + r * 144 + c * 16, g_ql + src);
    }
    CP_COMMIT();

    float yacc[2][4][4];
#pragma unroll
    for (int mf = 0; mf < 2; mf++)
#pragma unroll
        for (int nf = 0; nf < 4; nf++)
#pragma unroll
            for (int e = 0; e < 4; e++) yacc[mf][nf][e] = 0.f;
    float rsum[2][2] = {{0.f, 0.f}, {0.f, 0.f}};

    const int lr = lane >> 2, lc = (lane & 3) * 2;
    const int rowA = (lane & 7) | (((lane >> 3) & 1) << 3);
    const uint32_t colA16 = (lane >> 4) << 4;
    const int l2 = lane & 15;
    const uint32_t laneQ  = (uint32_t)(warp_m * 32 + rowA) * 144 + colA16;
    const uint32_t laneK  = (uint32_t)(warp_n * 64 + (l2 & 7)) * 144 + ((l2 >> 3) << 4);
    const uint32_t laneP  = (uint32_t)(warp_m * 32 + rowA) * 272 + colA16;
    const uint32_t laneV  = (uint32_t)(warp_n * 32 + (l2 & 7)) * 272 + ((l2 >> 3) << 4);

    for (int st = 0; st < 8; st++) {
        const int s0 = st * 128;
        // K (128x64 hi/lo) + Vt (64x128 hi/lo): 4096 chunks, 16/thread
#pragma unroll
        for (int i = 0; i < 16; i++) {
            const int idx = tid + i * 256;
            const int arr = idx >> 10, w = idx & 1023;
            if (arr < 2) {
                const int r = w >> 3, c = w & 7;
                const size_t src = (size_t)(bh * NT + s0 + r) * ND + c * 8;
                const uint32_t dst = sb + (arr ? AKL : AKH) + r * 144 + c * 16;
                cpasync16(dst, (arr ? g_kl : g_kh) + src);
            } else {
                const int r = w >> 4, c = w & 15;
                const size_t src = (size_t)(bh * ND + r) * NT + s0 + c * 8;
                const uint32_t dst = sb + (arr == 2 ? AVH : AVL) + r * 272 + c * 16;
                cpasync16(dst, (arr == 2 ? g_vth : g_vtl) + src);
            }
        }
        CP_COMMIT();
        asm volatile("cp.async.wait_group 0;" ::: "memory");
        __syncthreads();

        // ---- S = Q K^T (3-term split), warp tile 32 x 64 ----
        float sacc[2][8][4];
#pragma unroll
        for (int mf = 0; mf < 2; mf++)
#pragma unroll
            for (int nf = 0; nf < 8; nf++)
#pragma unroll
                for (int e = 0; e < 4; e++) sacc[mf][nf][e] = 0.f;

#pragma unroll
        for (int ks = 0; ks < 4; ks++) {
            uint32_t qh[2][4], ql[2][4], kh[8][2], kl[8][2];
#pragma unroll
            for (int mf = 0; mf < 2; mf++) {
                ldsm4(qh[mf], sb + AQH + laneQ + mf * 16 * 144 + ks * 32);
                ldsm4(ql[mf], sb + AQL + laneQ + mf * 16 * 144 + ks * 32);
            }
#pragma unroll
            for (int nf = 0; nf < 8; nf++) {
                ldsm2(kh[nf], sb + AKH + laneK + nf * 8 * 144 + ks * 32);
                ldsm2(kl[nf], sb + AKL + laneK + nf * 8 * 144 + ks * 32);
            }
#pragma unroll
            for (int mf = 0; mf < 2; mf++)
#pragma unroll
                for (int nf = 0; nf < 8; nf++) {
                    mma16816(sacc[mf][nf], qh[mf], kh[nf]);
                    mma16816(sacc[mf][nf], qh[mf], kl[nf]);
                    mma16816(sacc[mf][nf], ql[mf], kh[nf]);
                }
        }

        // ---- exp, attn store, P -> smem (bf16 hi/lo), rowsum ----
#pragma unroll
        for (int mf = 0; mf < 2; mf++)
#pragma unroll
            for (int half = 0; half < 2; half++) {
                const int tr = warp_m * 32 + mf * 16 + lr + half * 8;
                const int t = t0 + tr;
                const size_t brow = ((size_t)bh * NT + t) * NT;
                const size_t mrow = ((size_t)b  * NT + t) * NT;
#pragma unroll
                for (int nf = 0; nf < 8; nf++) {
                    const int sc = warp_n * 64 + nf * 8 + lc;
                    const int s = s0 + sc;
                    const float2 bb = *(const float2*)(bias + brow + s);
                    const float2 mm = *(const float2*)(mask + mrow + s);
                    float ta = fmaf(sacc[mf][nf][half*2+0], SC2E, (bb.x + mm.x) * L2E);
                    float tb = fmaf(sacc[mf][nf][half*2+1], SC2E, (bb.y + mm.y) * L2E);
                    ta = fmaxf(ta, -126.f);
                    tb = fmaxf(tb, -126.f);
                    const float p0 = fexp2(ta);
                    const float p1 = fexp2(tb);
                    rsum[mf][half] += p0 + p1;
                    float2 pw; pw.x = p0; pw.y = p1;
                    *(float2*)(attn + brow + s) = pw;
                    const __nv_bfloat16 ph0 = __float2bfloat16(p0);
                    const __nv_bfloat16 pl0 = __float2bfloat16(p0 - __bfloat162float(ph0));
                    const __nv_bfloat16 ph1 = __float2bfloat16(p1);
                    const __nv_bfloat16 pl1 = __float2bfloat16(p1 - __bfloat162float(ph1));
                    __nv_bfloat162 hh; hh.x = ph0; hh.y = ph1;
                    __nv_bfloat162 ll; ll.x = pl0; ll.y = pl1;
                    *(__nv_bfloat162*)(sa + APH + tr * 272 + sc * 2) = hh;
                    *(__nv_bfloat162*)(sa + APL + tr * 272 + sc * 2) = ll;
                }
            }
        __syncthreads();

        // ---- y += P V (3-term), warp tile 32 x 32, k = s (8 chunks) ----
#pragma unroll
        for (int ks = 0; ks < 8; ks++) {
            uint32_t ph[2][4], pl[2][4], vh[4][2], vl[4][2];
#pragma unroll
            for (int mf = 0; mf < 2; mf++) {
                ldsm4(ph[mf], sb + APH + laneP + mf * 16 * 272 + ks * 32);
                ldsm4(pl[mf], sb + APL + laneP + mf * 16 * 272 + ks * 32);
            }
#pragma unroll
            for (int nf = 0; nf < 4; nf++) {
                ldsm2(vh[nf], sb + AVH + laneV + nf * 8 * 272 + ks * 32);
                ldsm2(vl[nf], sb + AVL + laneV + nf * 8 * 272 + ks * 32);
            }
#pragma unroll
            for (int mf = 0; mf < 2; mf++)
#pragma unroll
                for (int nf = 0; nf < 4; nf++) {
                    mma16816(yacc[mf][nf], ph[mf], vh[nf]);
                    mma16816(yacc[mf][nf], ph[mf], vl[nf]);
                    mma16816(yacc[mf][nf], pl[mf], vh[nf]);
                }
        }
        __syncthreads();   // all reads of K/V/P done before next tile's loads
    }

    // ---- rowsum reduce: quad lanes share a row ----
#pragma unroll
    for (int mf = 0; mf < 2; mf++)
#pragma unroll
        for (int half = 0; half < 2; half++) {
            float r = rsum[mf][half];
            r += __shfl_xor_sync(0xffffffffu, r, 1);
            r += __shfl_xor_sync(0xffffffffu, r, 2);
            if ((lane & 3) == 0)
                RS[warp_n * 128 + warp_m * 32 + mf * 16 + lr + half * 8] = r;
        }
    __syncthreads();
    if (tid < 128) INV[tid] = 1.0f / (RS[tid] + RS[128 + tid]);
    __syncthreads();

    // ---- y epilogue ----
#pragma unroll
    for (int mf = 0; mf < 2; mf++)
#pragma unroll
        for (int half = 0; half < 2; half++) {
            const int tr = warp_m * 32 + mf * 16 + lr + half * 8;
            const float inv = INV[tr];
            const int t = t0 + tr;
#pragma unroll
            for (int nf = 0; nf < 4; nf++) {
                const int d = warp_n * 32 + nf * 8 + lc;
                float2 o;
                o.x = yacc[mf][nf][half*2+0] * inv;
                o.y = yacc[mf][nf][half*2+1] * inv;
                *(float2*)(g_yh + ((size_t)b * NT + t) * NC + h * ND + d) = o;
            }
        }

    // ---- normalize attn rows in place (block-local, L2-hot) ----
    for (int e = tid; e < 128 * 256; e += 256) {
        const int r = e >> 8, c = (e & 255) * 4;
        const float inv = INV[r];
        float4* p4 = (float4*)(attn + ((size_t)bh * NT + t0 + r) * NT + c);
        float4 v = *p4;
        v.x *= inv; v.y *= inv; v.z *= inv; v.w *= inv;
        *p4 = v;
    }
}

// ---------------- launch ---------------------------------------------------
extern "C" void kernel_launch(void* const* d_in, const int* in_sizes, int n_in,
                              void* d_out, int out_size)
{
    const float* x     = (const float*)d_in[0];
    const float* mask  = (const float*)d_in[1];
    const float* bias  = (const float*)d_in[2];
    const float* Wqkv  = (const float*)d_in[3];
    const float* bqkv  = (const float*)d_in[4];
    const float* Wproj = (const float*)d_in[5];
    const float* bproj = (const float*)d_in[6];

    float* y    = (float*)d_out;
    float* attn = y + (size_t)NB * NT * NC;

    cudaFuncSetAttribute(k_attn,    cudaFuncAttributeMaxDynamicSharedMemorySize, SMEMA);
    cudaFuncSetAttribute(k_gemm<1>, cudaFuncAttributeMaxDynamicSharedMemorySize, GSMEM2);
    cudaFuncSetAttribute(k_gemm<0>, cudaFuncAttributeMaxDynamicSharedMemorySize, GSMEM2);

    __nv_bfloat16 *xh, *xl, *wqh, *wql, *wph, *wpl, *yhh, *yhl;
    float *yh;
    cudaGetSymbolAddress((void**)&xh,  g_xh);  cudaGetSymbolAddress((void**)&xl,  g_xl);
    cudaGetSymbolAddress((void**)&wqh, g_wqh); cudaGetSymbolAddress((void**)&wql, g_wql);
    cudaGetSymbolAddress((void**)&wph, g_wph); cudaGetSymbolAddress((void**)&wpl, g_wpl);
    cudaGetSymbolAddress((void**)&yhh, g_yhh); cudaGetSymbolAddress((void**)&yhl, g_yhl);
    cudaGetSymbolAddress((void**)&yh,  g_yh);

    k_split <<<4096 * 768 / 1024, 256>>>(x, xh, xl);
    k_splitT<<<dim3(2304 / 32, 768 / 32), 256>>>(Wqkv, wqh, wql, 2304);
    k_splitT<<<dim3(768 / 32,  768 / 32), 256>>>(Wproj, wph, wpl, 768);

    k_gemm<1><<<dim3(2304 / 128, 4096 / 128), 256, GSMEM2>>>(xh, xl, wqh, wql, bqkv, nullptr);
    k_attn  <<<dim3(NT / 128, NH, NB), 256, SMEMA>>>(bias, mask, attn);
    k_split <<<4096 * 768 / 1024, 256>>>(yh, yhh, yhl);
    k_gemm<0><<<dim3(768 / 128, 4096 / 128), 256, GSMEM2>>>(yhh, yhl, wph, wpl, bproj, y);
}